// round 16
// baseline (speedup 1.0000x reference)
#include <cuda_runtime.h>
#include <cuda_bf16.h>
#include <cstdint>

// Problem constants
#define B_     32
#define IN_CH  16
#define OUT_CH 16
#define COND   8
#define T_OUT  65536
#define T_IN   65544              // T_OUT + 8 pad
#define WSZ    768                // 48 * 16 weights per batch

// Tiling: CTA = one batch x 512 timesteps; 8 warps x 8 eight-t tiles.
#define CTA_T    512
#define ROWF     520              // floats staged per channel row (512 + 8)
#define ROW_BYTES (ROWF * 4)      // 2080, multiple of 16
#define NCHUNK   6                // K = 48 = 6 chunks of k8

// Per-batch hypernet weights, tf32-pre-rounded fp32. w[b][k*16+o].
__device__ float g_w[B_ * WSZ];

// ---------------------------------------------------------------------------
// PTX helpers
// ---------------------------------------------------------------------------
__device__ __forceinline__ uint32_t smem_u32(const void* p) {
    uint32_t a;
    asm("{ .reg .u64 t; cvta.to.shared.u64 t, %1; cvt.u32.u64 %0, t; }"
        : "=r"(a) : "l"(p));
    return a;
}
__device__ __forceinline__ void mbar_init(uint32_t mb, uint32_t cnt) {
    asm volatile("mbarrier.init.shared.b64 [%0], %1;" :: "r"(mb), "r"(cnt) : "memory");
}
__device__ __forceinline__ void mbar_expect_tx(uint32_t mb, uint32_t bytes) {
    asm volatile("mbarrier.arrive.expect_tx.shared.b64 _, [%0], %1;"
                 :: "r"(mb), "r"(bytes) : "memory");
}
__device__ __forceinline__ void bulk_g2s(uint32_t dst, const void* src,
                                         uint32_t bytes, uint32_t mb) {
    asm volatile("cp.async.bulk.shared::cta.global.mbarrier::complete_tx::bytes "
                 "[%0], [%1], %2, [%3];"
                 :: "r"(dst), "l"(src), "r"(bytes), "r"(mb) : "memory");
}
__device__ __forceinline__ void mbar_wait(uint32_t mb, uint32_t parity) {
    asm volatile(
        "{\n\t.reg .pred P;\n\t"
        "W_%=:\n\t"
        "mbarrier.try_wait.parity.acquire.cta.shared::cta.b64 P, [%0], %1, 0x989680;\n\t"
        "@P bra.uni D_%=;\n\tbra.uni W_%=;\n\tD_%=:\n\t}"
        :: "r"(mb), "r"(parity) : "memory");
}
__device__ __forceinline__ uint32_t f2tf32(float v) {
    uint32_t r;
    asm("cvt.rna.tf32.f32 %0, %1;" : "=r"(r) : "f"(v));
    return r;
}

// m16n8k8 tf32 MMA: D(16x8 f32) += A(16x8 tf32, row) * B(8x8 tf32, col)
__device__ __forceinline__ void mma_tf32(float& c0, float& c1, float& c2, float& c3,
                                         uint32_t a0, uint32_t a1, uint32_t a2, uint32_t a3,
                                         uint32_t b0, uint32_t b1) {
    asm volatile(
        "mma.sync.aligned.m16n8k8.row.col.f32.tf32.tf32.f32 "
        "{%0,%1,%2,%3}, {%4,%5,%6,%7}, {%8,%9}, {%0,%1,%2,%3};"
        : "+f"(c0), "+f"(c1), "+f"(c2), "+f"(c3)
        : "r"(a0), "r"(a1), "r"(a2), "r"(a3), "r"(b0), "r"(b1));
}

// ---------------------------------------------------------------------------
// Kernel 1: hypernetwork. grid=(B_,3), block=256. Writes tf32-rounded weights.
// h is recomputed per CTA (16 threads, trivial) to triple j-parallelism.
// ---------------------------------------------------------------------------
__global__ void hyper_kernel(const float* __restrict__ p,
                             const float* __restrict__ W1,
                             const float* __restrict__ b1,
                             const float* __restrict__ W2,
                             const float* __restrict__ b2) {
    const int b   = blockIdx.x;
    const int tid = threadIdx.x;         // 0..255
    __shared__ float h[IN_CH];

    if (tid < IN_CH) {
        float s = b1[tid];
#pragma unroll
        for (int k = 0; k < COND; k++)
            s += p[b * COND + k] * W1[k * IN_CH + tid];
        h[tid] = (s > 0.0f) ? s : 0.2f * s;
    }
    __syncthreads();

    const int j = blockIdx.y * 256 + tid;    // 0..767 (= k*16 + o)
    float s = b2[j];
#pragma unroll
    for (int c = 0; c < IN_CH; c++)
        s += h[c] * W2[c * WSZ + j];

    g_w[b * WSZ + j] = __uint_as_float(f2tf32(s));   // RNA tf32, stored once
}

// ---------------------------------------------------------------------------
// Kernel 2: tf32 mma.sync conv.
//   grid = (128, 32), block = 256, 4 CTAs/SM (32 warps).
// A = per-batch weights (tf32-RNA, resident 24 regs).
// B = raw fp32 bits from staged x (HW truncates to tf32; no cvt on the hot
//     path). Each lane touches only 4 x rows -> hoisted base pointers; tile
//     loop fully unrolled so every LDS/STG is [reg + immediate].
// ---------------------------------------------------------------------------
__global__ __launch_bounds__(256, 4)
void conv_kernel(const float* __restrict__ x, float* __restrict__ y) {
    const int b    = blockIdx.y;
    const int tid  = threadIdx.x;                // 0..255
    const int warp = tid >> 5;                   // 0..7
    const int lane = tid & 31;
    const int row  = lane >> 2;                  // fragment group id (0..7)
    const int kq   = lane & 3;                   // k index within quad

    __shared__ __align__(16) float xs[IN_CH][ROWF];   // 33 KB staged x tile
    __shared__ float wsf[WSZ];
    __shared__ __align__(8) unsigned long long mbars[1];

    const uint32_t mbar0 = smem_u32(&mbars[0]);

    // ---- Stage x via cp.async.bulk ----
    if (tid == 0) {
        mbar_init(mbar0, 1);
        mbar_expect_tx(mbar0, IN_CH * ROW_BYTES);
        const float* xb = x + (size_t)(b * IN_CH) * T_IN + blockIdx.x * CTA_T;
#pragma unroll
        for (int c = 0; c < IN_CH; c++)
            bulk_g2s(smem_u32(&xs[c][0]), xb + (size_t)c * T_IN, ROW_BYTES, mbar0);
    }

    // ---- Weights: 3KB from g_w (tf32-rounded already) ----
#pragma unroll
    for (int it = 0; it < 3; it++)
        wsf[tid + 256 * it] = g_w[b * WSZ + tid + 256 * it];
    __syncthreads();

    // ---- Resident A fragments ----
    uint32_t af[NCHUNK][4];
#pragma unroll
    for (int kc = 0; kc < NCHUNK; kc++) {
        const int k0 = kc * 8 + kq;
        af[kc][0] = __float_as_uint(wsf[k0 * 16 + row]);
        af[kc][1] = __float_as_uint(wsf[k0 * 16 + row + 8]);
        af[kc][2] = __float_as_uint(wsf[(k0 + 4) * 16 + row]);
        af[kc][3] = __float_as_uint(wsf[(k0 + 4) * 16 + row + 8]);
    }

    // ---- Wait for x tile (per-warp, once) ----
    mbar_wait(mbar0, 0);

    // Hoisted per-lane bases: this lane only reads rows kq, kq+4, kq+8, kq+12
    // at column (warp*8 + row + 8) - 4*tap + 64*it  (imm offsets after unroll).
    const int col0 = warp * 8 + row + 8;
    const float* xp0 = &xs[kq][col0];
    const float* xp1 = &xs[kq + 4][col0];
    const float* xp2 = &xs[kq + 8][col0];
    const float* xp3 = &xs[kq + 12][col0];

    float* yp0 = y + (size_t)(b * OUT_CH + row) * T_OUT
                   + blockIdx.x * CTA_T + warp * 8 + 2 * kq;
    float* yp1 = yp0 + (size_t)8 * T_OUT;

#pragma unroll
    for (int it = 0; it < 8; it++) {
        const int off = it * 64;

        float a0 = 0.f, a1 = 0.f, a2 = 0.f, a3 = 0.f;   // chunks 0,2,4
        float e0 = 0.f, e1 = 0.f, e2 = 0.f, e3 = 0.f;   // chunks 1,3,5
#pragma unroll
        for (int s = 0; s < 3; s++) {
            const int d = off - 4 * s;                  // tap offset, imm
            mma_tf32(a0, a1, a2, a3,
                     af[2 * s][0], af[2 * s][1], af[2 * s][2], af[2 * s][3],
                     __float_as_uint(xp0[d]), __float_as_uint(xp1[d]));
            mma_tf32(e0, e1, e2, e3,
                     af[2 * s + 1][0], af[2 * s + 1][1],
                     af[2 * s + 1][2], af[2 * s + 1][3],
                     __float_as_uint(xp2[d]), __float_as_uint(xp3[d]));
        }

        *reinterpret_cast<float2*>(yp0 + off) = make_float2(a0 + e0, a1 + e1);
        *reinterpret_cast<float2*>(yp1 + off) = make_float2(a2 + e2, a3 + e3);
    }
}

// ---------------------------------------------------------------------------
extern "C" void kernel_launch(void* const* d_in, const int* in_sizes, int n_in,
                              void* d_out, int out_size) {
    const float* x  = (const float*)d_in[0];
    const float* p  = (const float*)d_in[1];
    const float* W1 = (const float*)d_in[2];
    const float* b1 = (const float*)d_in[3];
    const float* W2 = (const float*)d_in[4];
    const float* b2 = (const float*)d_in[5];
    float* y = (float*)d_out;

    dim3 hgrid(B_, 3);
    hyper_kernel<<<hgrid, 256>>>(p, W1, b1, W2, b2);

    dim3 grid(T_OUT / CTA_T, B_);
    conv_kernel<<<grid, 256>>>(x, y);
}